// round 2
// baseline (speedup 1.0000x reference)
#include <cuda_runtime.h>

#define Bsz 4
#define Ssz 128
#define Esz 512
#define Hn 8
#define HDsz 64
#define FFsz 2048
#define Lnum 4
#define Msz (Bsz*Ssz)   /* 512 rows */

// ---------------- scratch (static device memory, no allocations) ----------
__device__ float g_h[Msz*Esz];
__device__ float g_qkv[4*Msz*Esz];
__device__ float g_kproj[1024*Esz];
__device__ float g_A1[Bsz*Hn*Ssz*Ssz];
__device__ float g_A2[Bsz*Hn*Ssz*Ssz];
__device__ float g_ap[Bsz*Hn*Ssz*11];
__device__ float g_attnsum[Msz*Esz];
__device__ float g_tmp[Msz*Esz];
__device__ float g_ff[Msz*FFsz];

// ---------------- generic fp32 tiled GEMM: C[M,N] = A[M,K] @ W[N,K]^T -----
__device__ __forceinline__ void gemm_body(
    const float* __restrict__ A, const float* __restrict__ W,
    const float* __restrict__ bias, float* __restrict__ C,
    int M, int N, int K, int act)
{
    __shared__ float As[16][65];
    __shared__ float Ws[16][65];
    int tid = threadIdx.x;           // 256 threads
    int tx = tid & 15, ty = tid >> 4;
    int bm = blockIdx.y * 64, bn = blockIdx.x * 64;
    float acc[4][4] = {};
    for (int k0 = 0; k0 < K; k0 += 16) {
        #pragma unroll
        for (int l = 0; l < 4; l++) {
            int idx = tid + l * 256;        // 0..1023
            int m = idx >> 4, k = idx & 15;
            int gm = bm + m;
            As[k][m] = (gm < M) ? A[(size_t)gm * K + k0 + k] : 0.f;
            Ws[k][m] = W[(size_t)(bn + m) * K + k0 + k];   // N multiple of 64
        }
        __syncthreads();
        #pragma unroll
        for (int kk = 0; kk < 16; kk++) {
            float a[4], b[4];
            #pragma unroll
            for (int r = 0; r < 4; r++) a[r] = As[kk][ty * 4 + r];
            #pragma unroll
            for (int c = 0; c < 4; c++) b[c] = Ws[kk][tx * 4 + c];
            #pragma unroll
            for (int r = 0; r < 4; r++)
                #pragma unroll
                for (int c = 0; c < 4; c++)
                    acc[r][c] += a[r] * b[c];
        }
        __syncthreads();
    }
    #pragma unroll
    for (int r = 0; r < 4; r++) {
        int gm = bm + ty * 4 + r;
        if (gm >= M) continue;
        #pragma unroll
        for (int c = 0; c < 4; c++) {
            int gn = bn + tx * 4 + c;
            float v = acc[r][c];
            if (bias) v += bias[gn];
            if (act) v = fmaxf(v, 0.f);
            C[(size_t)gm * N + gn] = v;
        }
    }
}

__global__ void gemm_kernel(const float* __restrict__ A, const float* __restrict__ W,
                            const float* __restrict__ bias, float* __restrict__ C,
                            int M, int N, int K, int act)
{
    gemm_body(A, W, bias, C, M, N, K, act);
}

// 4 projections (q,k,vs,vo) packed on gridDim.z
__global__ void gemm_proj4(const float* __restrict__ A,
                           const float* __restrict__ W0, const float* __restrict__ W1,
                           const float* __restrict__ W2, const float* __restrict__ W3,
                           float* __restrict__ C, int M, int N, int K)
{
    const float* W = (blockIdx.z < 2) ? (blockIdx.z == 0 ? W0 : W1)
                                      : (blockIdx.z == 2 ? W2 : W3);
    gemm_body(A, W, nullptr, C + (size_t)blockIdx.z * M * N, M, N, K, 0);
}

// ---------------- fused scores + softmax + mask-split + pos-histogram -----
// block = (i, h, b), 128 threads (one per j)
__global__ void scores_kernel(const float* __restrict__ q, const float* __restrict__ k,
                              const float* __restrict__ kproj,
                              const int* __restrict__ know_adj,
                              const int* __restrict__ pos_mask,
                              const int* __restrict__ adj,
                              const int* __restrict__ smk, const int* __restrict__ omk,
                              const float* __restrict__ pe_k,
                              float* __restrict__ A1, float* __restrict__ A2,
                              float* __restrict__ attn_pos)
{
    int i = blockIdx.x, hh = blockIdx.y, b = blockIdx.z;
    int tid = threadIdx.x;                        // 0..127
    __shared__ float q_sh[64];
    __shared__ float ksh[128 * 65];               // (k_j + kproj[ka_ij]) rows
    __shared__ int   ka_sh[128];
    __shared__ float qr_sh[11];
    __shared__ float ap[11];
    __shared__ float red[4];

    if (tid < 64) q_sh[tid] = q[(size_t)(b * Ssz + i) * Esz + hh * HDsz + tid];
    {
        int ka = know_adj[(size_t)(b * Ssz + i) * Ssz + tid];
        ka_sh[tid] = min(max(ka, 0), 999);        // defensive clamp
    }
    if (tid < 11) ap[tid] = 0.f;
    __syncthreads();

    for (int idx = tid; idx < 128 * 64; idx += 128) {
        int j = idx >> 6, d = idx & 63;
        float kv = k[(size_t)(b * Ssz + j) * Esz + hh * HDsz + d];
        float kp = kproj[(size_t)ka_sh[j] * Esz + hh * HDsz + d];
        ksh[j * 65 + d] = kv + kp;
    }
    if (tid < 11) {
        float s = 0.f;
        #pragma unroll
        for (int d = 0; d < 64; d++) s += q_sh[d] * pe_k[tid * HDsz + d];
        qr_sh[tid] = s;
    }
    __syncthreads();

    int j = tid;
    float acc = 0.f;
    #pragma unroll
    for (int d = 0; d < 64; d++) acc += q_sh[d] * ksh[j * 65 + d];
    int p = pos_mask[i * Ssz + j];
    p = min(max(p, 0), 10);
    float s = (acc + qr_sh[p]) * 0.125f;   // hd^-0.5 = 1/8
    if (adj[(size_t)(b * Ssz + i) * Ssz + j] == 0) s -= 1e30f;

    // softmax over 128 (4 warps)
    float m = s;
    #pragma unroll
    for (int o = 16; o; o >>= 1) m = fmaxf(m, __shfl_xor_sync(0xffffffffu, m, o));
    if ((tid & 31) == 0) red[tid >> 5] = m;
    __syncthreads();
    m = fmaxf(fmaxf(red[0], red[1]), fmaxf(red[2], red[3]));
    float e = __expf(s - m);
    float sum = e;
    #pragma unroll
    for (int o = 16; o; o >>= 1) sum += __shfl_xor_sync(0xffffffffu, sum, o);
    __syncthreads();
    if ((tid & 31) == 0) red[tid >> 5] = sum;
    __syncthreads();
    sum = red[0] + red[1] + red[2] + red[3];
    float attn = e / sum;

    atomicAdd(&ap[p], attn);
    size_t base = ((size_t)(b * Hn + hh) * Ssz + i) * Ssz + j;
    A1[base] = attn * (float)smk[(size_t)(b * Ssz + i) * Ssz + j];
    A2[base] = attn * (float)omk[(size_t)(b * Ssz + i) * Ssz + j];
    __syncthreads();
    if (tid < 11) attn_pos[((size_t)(b * Hn + hh) * Ssz + i) * 11 + tid] = ap[tid];
}

// ---------------- attention value sum --------------------------------------
// block = (itile(4), h, b), 256 threads = 4 i-groups x 64 d
__global__ void attnsum_kernel(const float* __restrict__ vs, const float* __restrict__ vo,
                               const float* __restrict__ A1, const float* __restrict__ A2,
                               const float* __restrict__ attn_pos,
                               const float* __restrict__ pe_v,
                               float* __restrict__ outbuf)
{
    int itile = blockIdx.x, hh = blockIdx.y, b = blockIdx.z;
    int tid = threadIdx.x;
    int grp = tid >> 6, d = tid & 63;
    __shared__ float vsh[128 * 65];

    for (int idx = tid; idx < 128 * 64; idx += 256) {
        int j = idx >> 6, dd = idx & 63;
        vsh[j * 65 + dd] = vs[(size_t)(b * Ssz + j) * Esz + hh * HDsz + dd];
    }
    __syncthreads();

    float acc[8];
    #pragma unroll
    for (int it = 0; it < 8; it++) {
        int i = itile * 32 + it * 4 + grp;
        const float* a1 = A1 + ((size_t)(b * Hn + hh) * Ssz + i) * Ssz;
        float s = 0.f;
        #pragma unroll 4
        for (int jj = 0; jj < 128; jj++) s += a1[jj] * vsh[jj * 65 + d];
        acc[it] = s;
    }
    __syncthreads();
    for (int idx = tid; idx < 128 * 64; idx += 256) {
        int j = idx >> 6, dd = idx & 63;
        vsh[j * 65 + dd] = vo[(size_t)(b * Ssz + j) * Esz + hh * HDsz + dd];
    }
    __syncthreads();
    #pragma unroll
    for (int it = 0; it < 8; it++) {
        int i = itile * 32 + it * 4 + grp;
        const float* a2 = A2 + ((size_t)(b * Hn + hh) * Ssz + i) * Ssz;
        float s = acc[it];
        #pragma unroll 4
        for (int jj = 0; jj < 128; jj++) s += a2[jj] * vsh[jj * 65 + d];
        const float* app = attn_pos + ((size_t)(b * Hn + hh) * Ssz + i) * 11;
        #pragma unroll
        for (int p = 0; p < 11; p++) s += app[p] * pe_v[p * HDsz + d];
        outbuf[(size_t)(b * Ssz + i) * Esz + hh * HDsz + d] = s;
    }
}

// ---------------- residual + layernorm -------------------------------------
__global__ void ln_kernel(const float* __restrict__ x, const float* __restrict__ dlt,
                          const float* __restrict__ g, const float* __restrict__ bt,
                          float* __restrict__ dst)
{
    int row = blockIdx.x;
    int tid = threadIdx.x;   // 256
    __shared__ float red[8];
    const float* xr = x + (size_t)row * Esz;
    const float* dr = dlt + (size_t)row * Esz;
    float v0 = xr[tid] + dr[tid];
    float v1 = xr[tid + 256] + dr[tid + 256];
    float s = v0 + v1;
    #pragma unroll
    for (int o = 16; o; o >>= 1) s += __shfl_xor_sync(0xffffffffu, s, o);
    if ((tid & 31) == 0) red[tid >> 5] = s;
    __syncthreads();
    float mean = 0.f;
    #pragma unroll
    for (int w = 0; w < 8; w++) mean += red[w];
    mean *= (1.f / 512.f);
    __syncthreads();
    float e0 = v0 - mean, e1 = v1 - mean;
    float s2 = e0 * e0 + e1 * e1;
    #pragma unroll
    for (int o = 16; o; o >>= 1) s2 += __shfl_xor_sync(0xffffffffu, s2, o);
    if ((tid & 31) == 0) red[tid >> 5] = s2;
    __syncthreads();
    float var = 0.f;
    #pragma unroll
    for (int w = 0; w < 8; w++) var += red[w];
    var *= (1.f / 512.f);
    float rstd = rsqrtf(var + 1e-5f);
    dst[(size_t)row * Esz + tid]       = e0 * rstd * g[tid] + bt[tid];
    dst[(size_t)row * Esz + 256 + tid] = e1 * rstd * g[tid + 256] + bt[tid + 256];
}

__global__ void copy_kernel(float* __restrict__ dst, const float* __restrict__ src, int n)
{
    int i = blockIdx.x * blockDim.x + threadIdx.x;
    if (i < n) dst[i] = src[i];
}

// ---------------- host orchestration ---------------------------------------
extern "C" void kernel_launch(void* const* d_in, const int* in_sizes, int n_in,
                              void* d_out, int out_size)
{
    const float*     x        = (const float*)d_in[0];
    const int*       adj      = (const int*)d_in[1];
    const int*       smk      = (const int*)d_in[2];
    const int*       omk      = (const int*)d_in[3];
    const float*     knowledge= (const float*)d_in[4];
    const int*       know_adj = (const int*)d_in[5];   // int32 (JAX x64 disabled)
    const int*       pos_mask = (const int*)d_in[6];
    const float*     pe_k     = (const float*)d_in[7];
    const float*     pe_v     = (const float*)d_in[8];
    const float*     Wq       = (const float*)d_in[9];
    const float*     Wk       = (const float*)d_in[10];
    const float*     Wvs      = (const float*)d_in[11];
    const float*     Wvo      = (const float*)d_in[12];
    const float*     Wo       = (const float*)d_in[13];
    const float*     Wkn      = (const float*)d_in[14];
    const float*     ln1g     = (const float*)d_in[15];
    const float*     ln1b     = (const float*)d_in[16];
    const float*     w1       = (const float*)d_in[17];
    const float*     b1       = (const float*)d_in[18];
    const float*     w2       = (const float*)d_in[19];
    const float*     b2       = (const float*)d_in[20];
    const float*     ln2g     = (const float*)d_in[21];
    const float*     ln2b     = (const float*)d_in[22];
    float* out = (float*)d_out;

    float *h, *qkv, *kproj, *A1, *A2, *ap, *asum, *tmp, *ff;
    cudaGetSymbolAddress((void**)&h, g_h);
    cudaGetSymbolAddress((void**)&qkv, g_qkv);
    cudaGetSymbolAddress((void**)&kproj, g_kproj);
    cudaGetSymbolAddress((void**)&A1, g_A1);
    cudaGetSymbolAddress((void**)&A2, g_A2);
    cudaGetSymbolAddress((void**)&ap, g_ap);
    cudaGetSymbolAddress((void**)&asum, g_attnsum);
    cudaGetSymbolAddress((void**)&tmp, g_tmp);
    cudaGetSymbolAddress((void**)&ff, g_ff);

    copy_kernel<<<(Msz * Esz + 255) / 256, 256>>>(h, x, Msz * Esz);

    for (int l = 0; l < Lnum; l++) {
        const float* wq  = Wq  + (size_t)l * Esz * Esz;
        const float* wk  = Wk  + (size_t)l * Esz * Esz;
        const float* wvs = Wvs + (size_t)l * Esz * Esz;
        const float* wvo = Wvo + (size_t)l * Esz * Esz;
        const float* wo  = Wo  + (size_t)l * Esz * Esz;
        const float* wkn = Wkn + (size_t)l * Esz * Esz;

        // q,k,vs,vo projections
        gemm_proj4<<<dim3(8, 8, 4), 256>>>(h, wq, wk, wvs, wvo, qkv, Msz, Esz, Esz);
        // knowledge projection table [1000, 512]
        gemm_kernel<<<dim3(8, 16), 256>>>(knowledge, wkn, nullptr, kproj, 1000, Esz, Esz, 0);
        // fused scores / softmax / mask-split / pos histogram
        scores_kernel<<<dim3(Ssz, Hn, Bsz), 128>>>(
            qkv, qkv + (size_t)Msz * Esz, kproj, know_adj, pos_mask, adj, smk, omk,
            pe_k, A1, A2, ap);
        // attention value sum
        attnsum_kernel<<<dim3(4, Hn, Bsz), 256>>>(
            qkv + 2 * (size_t)Msz * Esz, qkv + 3 * (size_t)Msz * Esz,
            A1, A2, ap, pe_v, asum);
        // output projection
        gemm_kernel<<<dim3(8, 8), 256>>>(asum, wo, nullptr, tmp, Msz, Esz, Esz, 0);
        // residual + LN1 (in-place into h)
        ln_kernel<<<Msz, 256>>>(h, tmp, ln1g + l * Esz, ln1b + l * Esz, h);
        // FFN
        gemm_kernel<<<dim3(32, 8), 256>>>(h, w1 + (size_t)l * FFsz * Esz,
                                          b1 + l * FFsz, ff, Msz, FFsz, Esz, 1);
        gemm_kernel<<<dim3(8, 8), 256>>>(ff, w2 + (size_t)l * Esz * FFsz,
                                         b2 + l * Esz, tmp, Msz, Esz, FFsz, 0);
        // residual + LN2 (final layer writes straight to d_out)
        float* dst = (l == Lnum - 1) ? out : h;
        ln_kernel<<<Msz, 256>>>(h, tmp, ln2g + l * Esz, ln2b + l * Esz, dst);
    }
}

// round 3
// speedup vs baseline: 1.6311x; 1.6311x over previous
#include <cuda_runtime.h>

#define Bsz 4
#define Ssz 128
#define Esz 512
#define Hn 8
#define HDsz 64
#define FFsz 2048
#define Lnum 4
#define Msz (Bsz*Ssz)   /* 512 rows */

// ---------------- scratch (static device memory, no allocations) ----------
__device__ float g_h[Msz*Esz];
__device__ float g_qkv[4*Msz*Esz];
__device__ float g_kproj[1024*Esz];
__device__ float g_A1[Bsz*Hn*Ssz*Ssz];
__device__ float g_A2[Bsz*Hn*Ssz*Ssz];
__device__ float g_ap[Bsz*Hn*Ssz*11];
__device__ float g_attnsum[Msz*Esz];
__device__ float g_tmp[Msz*Esz];
__device__ float g_ff[Msz*FFsz];
__device__ float g_part[4*512*512];   // split-K partials (4 MB)

// ---------------- fp32 tiled GEMM: C[M,N] = A[M,K] @ W[N,K]^T --------------
// 64x64 tile, float4 smem traffic, K range [kbeg,kend)
__device__ __forceinline__ void gemm_body(
    const float* __restrict__ A, const float* __restrict__ W,
    const float* __restrict__ bias, float* __restrict__ C,
    int M, int N, int kbeg, int kend, int K, int act)
{
    __shared__ float As[16][68];
    __shared__ float Ws[16][68];
    int tid = threadIdx.x;           // 256 threads
    int tx = tid & 15, ty = tid >> 4;
    int bm = blockIdx.y * 64, bn = blockIdx.x * 64;
    int m_l = tid >> 2, k4 = (tid & 3) * 4;
    float acc[4][4] = {};
    for (int k0 = kbeg; k0 < kend; k0 += 16) {
        int gm = bm + m_l;
        float4 av = (gm < M) ? *(const float4*)(A + (size_t)gm * K + k0 + k4)
                             : make_float4(0.f, 0.f, 0.f, 0.f);
        float4 wv = *(const float4*)(W + (size_t)(bn + m_l) * K + k0 + k4);
        As[k4 + 0][m_l] = av.x; As[k4 + 1][m_l] = av.y;
        As[k4 + 2][m_l] = av.z; As[k4 + 3][m_l] = av.w;
        Ws[k4 + 0][m_l] = wv.x; Ws[k4 + 1][m_l] = wv.y;
        Ws[k4 + 2][m_l] = wv.z; Ws[k4 + 3][m_l] = wv.w;
        __syncthreads();
        #pragma unroll
        for (int kk = 0; kk < 16; kk++) {
            float4 a = *(const float4*)&As[kk][ty * 4];
            float4 bv = *(const float4*)&Ws[kk][tx * 4];
            float ar[4] = {a.x, a.y, a.z, a.w};
            float br[4] = {bv.x, bv.y, bv.z, bv.w};
            #pragma unroll
            for (int r = 0; r < 4; r++)
                #pragma unroll
                for (int c = 0; c < 4; c++)
                    acc[r][c] += ar[r] * br[c];
        }
        __syncthreads();
    }
    #pragma unroll
    for (int r = 0; r < 4; r++) {
        int gm = bm + ty * 4 + r;
        if (gm >= M) continue;
        #pragma unroll
        for (int c = 0; c < 4; c++) {
            int gn = bn + tx * 4 + c;
            float v = acc[r][c];
            if (bias) v += bias[gn];
            if (act) v = fmaxf(v, 0.f);
            C[(size_t)gm * N + gn] = v;
        }
    }
}

__global__ void gemm_kernel(const float* __restrict__ A, const float* __restrict__ W,
                            const float* __restrict__ bias, float* __restrict__ C,
                            int M, int N, int K, int act)
{
    gemm_body(A, W, bias, C, M, N, 0, K, K, act);
}

// split-K: grid.z chunks, partials to part[z*M*N ...]
__global__ void gemm_splitk(const float* __restrict__ A, const float* __restrict__ W,
                            float* __restrict__ part, int M, int N, int K, int KS)
{
    int chunk = K / KS;
    int z = blockIdx.z;
    gemm_body(A, W, nullptr, part + (size_t)z * M * N,
              M, N, z * chunk, (z + 1) * chunk, K, 0);
}

// deterministic partial reduce (+bias, +relu), float4
__global__ void reduce_kernel(const float* __restrict__ part, const float* __restrict__ bias,
                              float* __restrict__ C, int MN, int N, int KS, int act)
{
    int i = (blockIdx.x * 256 + threadIdx.x) * 4;
    if (i >= MN) return;
    float4 s = *(const float4*)(part + i);
    for (int z = 1; z < KS; z++) {
        float4 t = *(const float4*)(part + (size_t)z * MN + i);
        s.x += t.x; s.y += t.y; s.z += t.z; s.w += t.w;
    }
    if (bias) {
        int n = i % N;
        s.x += bias[n]; s.y += bias[n + 1]; s.z += bias[n + 2]; s.w += bias[n + 3];
    }
    if (act) {
        s.x = fmaxf(s.x, 0.f); s.y = fmaxf(s.y, 0.f);
        s.z = fmaxf(s.z, 0.f); s.w = fmaxf(s.w, 0.f);
    }
    *(float4*)(C + i) = s;
}

// 4 projections (q,k,vs,vo) packed on gridDim.z
__global__ void gemm_proj4(const float* __restrict__ A,
                           const float* __restrict__ W0, const float* __restrict__ W1,
                           const float* __restrict__ W2, const float* __restrict__ W3,
                           float* __restrict__ C, int M, int N, int K)
{
    const float* W = (blockIdx.z < 2) ? (blockIdx.z == 0 ? W0 : W1)
                                      : (blockIdx.z == 2 ? W2 : W3);
    gemm_body(A, W, nullptr, C + (size_t)blockIdx.z * M * N, M, N, 0, K, K, 0);
}

// ---------------- fused scores + softmax + mask-split + pos-histogram -----
// block = (i, b), 256 threads, ALL 8 heads per block
__global__ void scores_kernel(const float* __restrict__ q, const float* __restrict__ k,
                              const float* __restrict__ kproj,
                              const int* __restrict__ know_adj,
                              const int* __restrict__ pos_mask,
                              const int* __restrict__ adj,
                              const int* __restrict__ smk, const int* __restrict__ omk,
                              const float* __restrict__ pe_k,
                              float* __restrict__ A1, float* __restrict__ A2,
                              float* __restrict__ attn_pos)
{
    int i = blockIdx.x, b = blockIdx.y;
    int tid = threadIdx.x;                  // 0..255
    __shared__ float q_sh[512];
    __shared__ float sc[8 * 128];           // dots, later attn
    __shared__ float qr[8 * 11];
    __shared__ int   ka_sh[128];
    __shared__ int   p_sh[128];

    q_sh[tid]       = q[(size_t)(b * Ssz + i) * Esz + tid];
    q_sh[tid + 256] = q[(size_t)(b * Ssz + i) * Esz + tid + 256];
    if (tid < 128) {
        int ka = know_adj[(size_t)(b * Ssz + i) * Ssz + tid];
        ka_sh[tid] = min(max(ka, 0), 999);
        int p = pos_mask[i * Ssz + tid];
        p_sh[tid] = min(max(p, 0), 10);
    }
    __syncthreads();

    // ---- dot phase: thread (j, half) computes 4 head-dots over 256 floats
    {
        int j  = tid & 127;
        int hb = tid >> 7;                  // 0 or 1 -> heads 4*hb..4*hb+3
        const float4* krow = (const float4*)(k + (size_t)(b * Ssz + j) * Esz + hb * 256);
        const float4* kprow = (const float4*)(kproj + (size_t)ka_sh[j] * Esz + hb * 256);
        const float4* qv = (const float4*)(q_sh + hb * 256);
        #pragma unroll
        for (int hh = 0; hh < 4; hh++) {
            float a = 0.f;
            #pragma unroll
            for (int u = 0; u < 16; u++) {
                int v = hh * 16 + u;
                float4 kv = krow[v];
                float4 kp = kprow[v];
                float4 qq = qv[v];
                a += qq.x * (kv.x + kp.x) + qq.y * (kv.y + kp.y)
                   + qq.z * (kv.z + kp.z) + qq.w * (kv.w + kp.w);
            }
            sc[(4 * hb + hh) * 128 + j] = a;
        }
    }
    // ---- qr[h][p] = q_h . pe_k[p]
    if (tid < 88) {
        int h = tid / 11, p = tid % 11;
        float s = 0.f;
        const float4* pk = (const float4*)(pe_k + p * HDsz);
        const float4* qv = (const float4*)(q_sh + h * 64);
        #pragma unroll
        for (int v = 0; v < 16; v++) {
            float4 e = pk[v], qq = qv[v];
            s += qq.x * e.x + qq.y * e.y + qq.z * e.z + qq.w * e.w;
        }
        qr[h * 11 + p] = s;
    }
    __syncthreads();

    // ---- softmax: warp w handles head w; lane covers j = l, l+32, l+64, l+96
    {
        int w = tid >> 5, l = tid & 31;
        float s[4];
        float m = -3.4e38f;
        #pragma unroll
        for (int t = 0; t < 4; t++) {
            int j = l + 32 * t;
            float ss = (sc[w * 128 + j] + qr[w * 11 + p_sh[j]]) * 0.125f;
            if (adj[(size_t)(b * Ssz + i) * Ssz + j] == 0) ss -= 1e30f;
            s[t] = ss;
            m = fmaxf(m, ss);
        }
        #pragma unroll
        for (int o = 16; o; o >>= 1) m = fmaxf(m, __shfl_xor_sync(0xffffffffu, m, o));
        float sum = 0.f;
        float e[4];
        #pragma unroll
        for (int t = 0; t < 4; t++) { e[t] = __expf(s[t] - m); sum += e[t]; }
        #pragma unroll
        for (int o = 16; o; o >>= 1) sum += __shfl_xor_sync(0xffffffffu, sum, o);
        float inv = 1.f / sum;
        size_t rbase = ((size_t)(b * Hn + w) * Ssz + i) * Ssz;
        #pragma unroll
        for (int t = 0; t < 4; t++) {
            int j = l + 32 * t;
            float attn = e[t] * inv;
            A1[rbase + j] = attn * (float)smk[(size_t)(b * Ssz + i) * Ssz + j];
            A2[rbase + j] = attn * (float)omk[(size_t)(b * Ssz + i) * Ssz + j];
            sc[w * 128 + j] = attn;      // reuse for histogram
        }
    }
    __syncthreads();

    // ---- deterministic position histogram
    if (tid < 88) {
        int h = tid / 11, p = tid % 11;
        float s = 0.f;
        for (int j = 0; j < 128; j++)
            if (p_sh[j] == p) s += sc[h * 128 + j];
        attn_pos[((size_t)(b * Hn + h) * Ssz + i) * 11 + p] = s;
    }
}

// ---------------- attention value sum --------------------------------------
// block = (itile(4), h, b), 256 threads = 4 i-groups x 64 d
__global__ void attnsum_kernel(const float* __restrict__ vs, const float* __restrict__ vo,
                               const float* __restrict__ A1, const float* __restrict__ A2,
                               const float* __restrict__ attn_pos,
                               const float* __restrict__ pe_v,
                               float* __restrict__ outbuf)
{
    int itile = blockIdx.x, hh = blockIdx.y, b = blockIdx.z;
    int tid = threadIdx.x;
    int grp = tid >> 6, d = tid & 63;
    __shared__ float vsh[128 * 65];

    for (int idx = tid; idx < 128 * 64; idx += 256) {
        int j = idx >> 6, dd = idx & 63;
        vsh[j * 65 + dd] = vs[(size_t)(b * Ssz + j) * Esz + hh * HDsz + dd];
    }
    __syncthreads();

    float acc[8];
    #pragma unroll
    for (int it = 0; it < 8; it++) {
        int i = itile * 32 + it * 4 + grp;
        const float* a1 = A1 + ((size_t)(b * Hn + hh) * Ssz + i) * Ssz;
        float s = 0.f;
        #pragma unroll 4
        for (int jj = 0; jj < 128; jj++) s += a1[jj] * vsh[jj * 65 + d];
        acc[it] = s;
    }
    __syncthreads();
    for (int idx = tid; idx < 128 * 64; idx += 256) {
        int j = idx >> 6, dd = idx & 63;
        vsh[j * 65 + dd] = vo[(size_t)(b * Ssz + j) * Esz + hh * HDsz + dd];
    }
    __syncthreads();
    #pragma unroll
    for (int it = 0; it < 8; it++) {
        int i = itile * 32 + it * 4 + grp;
        const float* a2 = A2 + ((size_t)(b * Hn + hh) * Ssz + i) * Ssz;
        float s = acc[it];
        #pragma unroll 4
        for (int jj = 0; jj < 128; jj++) s += a2[jj] * vsh[jj * 65 + d];
        const float* app = attn_pos + ((size_t)(b * Hn + hh) * Ssz + i) * 11;
        #pragma unroll
        for (int p = 0; p < 11; p++) s += app[p] * pe_v[p * HDsz + d];
        outbuf[(size_t)(b * Ssz + i) * Esz + hh * HDsz + d] = s;
    }
}

// ---------------- residual + layernorm -------------------------------------
__global__ void ln_kernel(const float* __restrict__ x, const float* __restrict__ dlt,
                          const float* __restrict__ g, const float* __restrict__ bt,
                          float* __restrict__ dst)
{
    int row = blockIdx.x;
    int tid = threadIdx.x;   // 256
    __shared__ float red[8];
    const float* xr = x + (size_t)row * Esz;
    const float* dr = dlt + (size_t)row * Esz;
    float v0 = xr[tid] + dr[tid];
    float v1 = xr[tid + 256] + dr[tid + 256];
    float s = v0 + v1;
    #pragma unroll
    for (int o = 16; o; o >>= 1) s += __shfl_xor_sync(0xffffffffu, s, o);
    if ((tid & 31) == 0) red[tid >> 5] = s;
    __syncthreads();
    float mean = 0.f;
    #pragma unroll
    for (int w = 0; w < 8; w++) mean += red[w];
    mean *= (1.f / 512.f);
    __syncthreads();
    float e0 = v0 - mean, e1 = v1 - mean;
    float s2 = e0 * e0 + e1 * e1;
    #pragma unroll
    for (int o = 16; o; o >>= 1) s2 += __shfl_xor_sync(0xffffffffu, s2, o);
    if ((tid & 31) == 0) red[tid >> 5] = s2;
    __syncthreads();
    float var = 0.f;
    #pragma unroll
    for (int w = 0; w < 8; w++) var += red[w];
    var *= (1.f / 512.f);
    float rstd = rsqrtf(var + 1e-5f);
    dst[(size_t)row * Esz + tid]       = e0 * rstd * g[tid] + bt[tid];
    dst[(size_t)row * Esz + 256 + tid] = e1 * rstd * g[tid + 256] + bt[tid + 256];
}

__global__ void copy_kernel(float* __restrict__ dst, const float* __restrict__ src, int n)
{
    int i = blockIdx.x * blockDim.x + threadIdx.x;
    if (i < n) dst[i] = src[i];
}

// ---------------- host orchestration ---------------------------------------
extern "C" void kernel_launch(void* const* d_in, const int* in_sizes, int n_in,
                              void* d_out, int out_size)
{
    const float*     x        = (const float*)d_in[0];
    const int*       adj      = (const int*)d_in[1];
    const int*       smk      = (const int*)d_in[2];
    const int*       omk      = (const int*)d_in[3];
    const float*     knowledge= (const float*)d_in[4];
    const int*       know_adj = (const int*)d_in[5];   // int32 (JAX x64 disabled)
    const int*       pos_mask = (const int*)d_in[6];
    const float*     pe_k     = (const float*)d_in[7];
    const float*     pe_v     = (const float*)d_in[8];
    const float*     Wq       = (const float*)d_in[9];
    const float*     Wk       = (const float*)d_in[10];
    const float*     Wvs      = (const float*)d_in[11];
    const float*     Wvo      = (const float*)d_in[12];
    const float*     Wo       = (const float*)d_in[13];
    const float*     Wkn      = (const float*)d_in[14];
    const float*     ln1g     = (const float*)d_in[15];
    const float*     ln1b     = (const float*)d_in[16];
    const float*     w1       = (const float*)d_in[17];
    const float*     b1       = (const float*)d_in[18];
    const float*     w2       = (const float*)d_in[19];
    const float*     b2       = (const float*)d_in[20];
    const float*     ln2g     = (const float*)d_in[21];
    const float*     ln2b     = (const float*)d_in[22];
    float* out = (float*)d_out;

    float *h, *qkv, *kproj, *A1, *A2, *ap, *asum, *tmp, *ff, *part;
    cudaGetSymbolAddress((void**)&h, g_h);
    cudaGetSymbolAddress((void**)&qkv, g_qkv);
    cudaGetSymbolAddress((void**)&kproj, g_kproj);
    cudaGetSymbolAddress((void**)&A1, g_A1);
    cudaGetSymbolAddress((void**)&A2, g_A2);
    cudaGetSymbolAddress((void**)&ap, g_ap);
    cudaGetSymbolAddress((void**)&asum, g_attnsum);
    cudaGetSymbolAddress((void**)&tmp, g_tmp);
    cudaGetSymbolAddress((void**)&ff, g_ff);
    cudaGetSymbolAddress((void**)&part, g_part);

    copy_kernel<<<(Msz * Esz + 255) / 256, 256>>>(h, x, Msz * Esz);

    for (int l = 0; l < Lnum; l++) {
        const float* wq  = Wq  + (size_t)l * Esz * Esz;
        const float* wk  = Wk  + (size_t)l * Esz * Esz;
        const float* wvs = Wvs + (size_t)l * Esz * Esz;
        const float* wvo = Wvo + (size_t)l * Esz * Esz;
        const float* wo  = Wo  + (size_t)l * Esz * Esz;
        const float* wkn = Wkn + (size_t)l * Esz * Esz;

        // q,k,vs,vo projections (256 CTAs)
        gemm_proj4<<<dim3(8, 8, 4), 256>>>(h, wq, wk, wvs, wvo, qkv, Msz, Esz, Esz);
        // knowledge projection table [1000, 512], split-K=2 (256 CTAs)
        gemm_splitk<<<dim3(8, 16, 2), 256>>>(knowledge, wkn, part, 1000, Esz, Esz, 2);
        reduce_kernel<<<(1000 * Esz / 4 + 255) / 256, 256>>>(part, nullptr, kproj,
                                                             1000 * Esz, Esz, 2, 0);
        // fused scores / softmax / mask-split / pos histogram (all heads per CTA)
        scores_kernel<<<dim3(Ssz, Bsz), 256>>>(
            qkv, qkv + (size_t)Msz * Esz, kproj, know_adj, pos_mask, adj, smk, omk,
            pe_k, A1, A2, ap);
        // attention value sum
        attnsum_kernel<<<dim3(4, Hn, Bsz), 256>>>(
            qkv + 2 * (size_t)Msz * Esz, qkv + 3 * (size_t)Msz * Esz,
            A1, A2, ap, pe_v, asum);
        // output projection, split-K=4 (256 CTAs)
        gemm_splitk<<<dim3(8, 8, 4), 256>>>(asum, wo, part, Msz, Esz, Esz, 4);
        reduce_kernel<<<(Msz * Esz / 4 + 255) / 256, 256>>>(part, nullptr, tmp,
                                                            Msz * Esz, Esz, 4, 0);
        // residual + LN1 (in-place into h)
        ln_kernel<<<Msz, 256>>>(h, tmp, ln1g + l * Esz, ln1b + l * Esz, h);
        // FFN
        gemm_kernel<<<dim3(32, 8), 256>>>(h, w1 + (size_t)l * FFsz * Esz,
                                          b1 + l * FFsz, ff, Msz, FFsz, Esz, 1);
        gemm_splitk<<<dim3(8, 8, 4), 256>>>(ff, w2 + (size_t)l * Esz * FFsz,
                                            part, Msz, Esz, FFsz, 4);
        reduce_kernel<<<(Msz * Esz / 4 + 255) / 256, 256>>>(part, b2 + l * Esz, tmp,
                                                            Msz * Esz, Esz, 4, 0);
        // residual + LN2 (final layer writes straight to d_out)
        float* dst = (l == Lnum - 1) ? out : h;
        ln_kernel<<<Msz, 256>>>(h, tmp, ln2g + l * Esz, ln2b + l * Esz, dst);
    }
}